// round 2
// baseline (speedup 1.0000x reference)
#include <cuda_runtime.h>
#include <math.h>

// Problem constants (fixed shapes for this problem instance)
#define NTOK 65536   // B * Lq = 4 * 16384
#define LQ   16384
#define DM   128
#define NHH  4
#define NPP  4
#define HDD  32
#define FFD  512
#define GW   128
#define GH   128

// ---------------- device scratch (static, no allocations) ----------------
__device__ __align__(16) float g_q[NTOK * DM];          // running query (33.5 MB)
__device__ __align__(16) float g_value[NTOK * DM];      // value tensor  (33.5 MB)
__device__ __align__(16) float g_attn[NTOK * DM];       // sampled attn  (33.5 MB)
__device__ __align__(16) float g_hidden[NTOK * FFD];    // FFN hidden    (128 MB)
__device__ float g_px[NTOK * NHH * NPP];                // sample x (pixel coords)
__device__ float g_py[NTOK * NHH * NPP];                // sample y
__device__ float g_aw[NTOK * NHH * NPP];                // softmaxed attn weights

// ---------------------------------------------------------------------------
// Kernel 1: sampling params. qin = q + pos; off = qin@so_w+so_b (32 outs),
// logits = qin@aw_w+aw_b (16 outs, softmax over groups of 4).
// px = (q % W) + off_x ; py = (q / W) + off_y  (align_corners=False algebra)
// Block: 256 threads handles 32 tokens.
// ---------------------------------------------------------------------------
__global__ void __launch_bounds__(256) params_kernel(
    const float* __restrict__ pos,
    const float* __restrict__ so_w, const float* __restrict__ so_b,
    const float* __restrict__ aw_w, const float* __restrict__ aw_b)
{
    __shared__ float Ws[DM * 48];     // combined [k][48] weights (24.0 KB)
    __shared__ float qs[DM * 33];     // qin transposed [k][tok], pad 33 (16.5 KB)
    __shared__ float outs[32 * 49];   // per-token 48 outputs (6.1 KB)

    const int tid = threadIdx.x;
    const int t0 = blockIdx.x * 32;

    // load combined weight matrix
    for (int i = tid; i < DM * 48; i += 256) {
        int k = i / 48, o = i % 48;
        Ws[i] = (o < 32) ? so_w[k * 32 + o] : aw_w[k * 16 + (o - 32)];
    }
    // load qin (transposed into smem)
    for (int i = tid; i < 32 * DM; i += 256) {
        int tok = i >> 7, k = i & 127;
        int gq = t0 + tok;
        qs[k * 33 + tok] = g_q[gq * DM + k] + pos[gq * DM + k];
    }
    __syncthreads();

    const int tok = tid >> 3;       // 0..31
    const int og  = tid & 7;        // 0..7 -> outputs og*6 .. og*6+5
    float acc[6];
#pragma unroll
    for (int j = 0; j < 6; j++) {
        int o = og * 6 + j;
        acc[j] = (o < 32) ? so_b[o] : aw_b[o - 32];
    }
#pragma unroll 8
    for (int k = 0; k < DM; k++) {
        float a = qs[k * 33 + tok];
#pragma unroll
        for (int j = 0; j < 6; j++)
            acc[j] += a * Ws[k * 48 + og * 6 + j];
    }
#pragma unroll
    for (int j = 0; j < 6; j++) outs[tok * 49 + og * 6 + j] = acc[j];
    __syncthreads();

    if (tid < 128) {
        int tk = tid >> 2, h = tid & 3;
        int gq = t0 + tk;
        // softmax over the 4 points of this head
        float lg0 = outs[tk * 49 + 32 + h * 4 + 0];
        float lg1 = outs[tk * 49 + 32 + h * 4 + 1];
        float lg2 = outs[tk * 49 + 32 + h * 4 + 2];
        float lg3 = outs[tk * 49 + 32 + h * 4 + 3];
        float m = fmaxf(fmaxf(lg0, lg1), fmaxf(lg2, lg3));
        float e0 = expf(lg0 - m), e1 = expf(lg1 - m), e2 = expf(lg2 - m), e3 = expf(lg3 - m);
        float inv = 1.0f / (e0 + e1 + e2 + e3);
        // pixel-space reference point
        float jx = (float)(gq & (GW - 1));
        float iy = (float)((gq >> 7) & (GH - 1));
        int pbase = gq * 16 + h * 4;
#pragma unroll
        for (int p = 0; p < 4; p++) {
            g_px[pbase + p] = jx + outs[tk * 49 + h * 8 + p * 2 + 0];
            g_py[pbase + p] = iy + outs[tk * 49 + h * 8 + p * 2 + 1];
        }
        g_aw[pbase + 0] = e0 * inv;
        g_aw[pbase + 1] = e1 * inv;
        g_aw[pbase + 2] = e2 * inv;
        g_aw[pbase + 3] = e3 * inv;
    }
}

// ---------------------------------------------------------------------------
// Tiled fp32 GEMM: out[M][Ntot] = A[M][K] @ Wt[K][Ntot] + bias, optional ReLU,
// optional fused residual + LayerNorm (requires Ntot==128 covered by one block
// column, i.e. grid.y == 1). Tile 64 x 128, BK = 16, 256 threads, 8x4 per thr.
// Row ownership: warp w owns rows w*8..w*8+7; lane owns cols lane*4..lane*4+3
// -> full 128-wide row lives in one warp, LN via shuffle reduction.
// ---------------------------------------------------------------------------
template<int K, bool RELU, bool LN>
__global__ void __launch_bounds__(256) gemm_k(
    const float* __restrict__ A, const float* __restrict__ Wt,
    const float* __restrict__ bias, const float* __restrict__ resid,
    const float* __restrict__ lng, const float* __restrict__ lnb,
    float* __restrict__ out, int Ntot)
{
    __shared__ float As[16 * 65];                 // [k][row], padded
    __shared__ __align__(16) float Bs[16 * 128];  // [k][n]

    const int tid  = threadIdx.x;
    const int row0 = blockIdx.x * 64;
    const int n0   = blockIdx.y * 128;
    const int warp = tid >> 5, lane = tid & 31;

    float acc[8][4];
#pragma unroll
    for (int i = 0; i < 8; i++)
#pragma unroll
        for (int j = 0; j < 4; j++) acc[i][j] = 0.0f;

    const int arow = tid >> 2;            // 0..63
    const int akk  = (tid & 3) * 4;       // 0,4,8,12
    const float* Aptr = A + (size_t)(row0 + arow) * K + akk;

    for (int kt = 0; kt < K; kt += 16) {
        // A tile (vectorized load, transposed store)
        float4 av = *(const float4*)(Aptr + kt);
        As[(akk + 0) * 65 + arow] = av.x;
        As[(akk + 1) * 65 + arow] = av.y;
        As[(akk + 2) * 65 + arow] = av.z;
        As[(akk + 3) * 65 + arow] = av.w;
        // B tile (row-major, coalesced)
#pragma unroll
        for (int i = 0; i < 8; i++) {
            int idx = tid + i * 256;           // 0..2047
            int bk = idx >> 7, bn = idx & 127;
            Bs[bk * 128 + bn] = Wt[(size_t)(kt + bk) * Ntot + n0 + bn];
        }
        __syncthreads();
#pragma unroll
        for (int k = 0; k < 16; k++) {
            float4 b4 = *(const float4*)&Bs[k * 128 + lane * 4];
#pragma unroll
            for (int i = 0; i < 8; i++) {
                float a = As[k * 65 + warp * 8 + i];
                acc[i][0] += a * b4.x;
                acc[i][1] += a * b4.y;
                acc[i][2] += a * b4.z;
                acc[i][3] += a * b4.w;
            }
        }
        __syncthreads();
    }

    float4 bv = *(const float4*)&bias[n0 + lane * 4];

    if (LN) {
        float4 gv  = *(const float4*)&lng[lane * 4];
        float4 bev = *(const float4*)&lnb[lane * 4];
#pragma unroll
        for (int i = 0; i < 8; i++) {
            int r = row0 + warp * 8 + i;
            float4 rs = *(const float4*)&resid[(size_t)r * 128 + lane * 4];
            float v0 = acc[i][0] + bv.x + rs.x;
            float v1 = acc[i][1] + bv.y + rs.y;
            float v2 = acc[i][2] + bv.z + rs.z;
            float v3 = acc[i][3] + bv.w + rs.w;
            float s  = v0 + v1 + v2 + v3;
            float s2 = v0 * v0 + v1 * v1 + v2 * v2 + v3 * v3;
#pragma unroll
            for (int o = 16; o > 0; o >>= 1) {
                s  += __shfl_xor_sync(0xffffffffu, s,  o);
                s2 += __shfl_xor_sync(0xffffffffu, s2, o);
            }
            float mean = s * 0.0078125f;                 // /128
            float var  = s2 * 0.0078125f - mean * mean;
            float inv  = rsqrtf(var + 1e-5f);
            float4 o4;
            o4.x = (v0 - mean) * inv * gv.x + bev.x;
            o4.y = (v1 - mean) * inv * gv.y + bev.y;
            o4.z = (v2 - mean) * inv * gv.z + bev.z;
            o4.w = (v3 - mean) * inv * gv.w + bev.w;
            *(float4*)&out[(size_t)r * 128 + lane * 4] = o4;
        }
    } else {
#pragma unroll
        for (int i = 0; i < 8; i++) {
            int r = row0 + warp * 8 + i;
            float4 o4;
            o4.x = acc[i][0] + bv.x;
            o4.y = acc[i][1] + bv.y;
            o4.z = acc[i][2] + bv.z;
            o4.w = acc[i][3] + bv.w;
            if (RELU) {
                o4.x = fmaxf(o4.x, 0.0f); o4.y = fmaxf(o4.y, 0.0f);
                o4.z = fmaxf(o4.z, 0.0f); o4.w = fmaxf(o4.w, 0.0f);
            }
            *(float4*)&out[(size_t)r * Ntot + n0 + lane * 4] = o4;
        }
    }
}

// ---------------------------------------------------------------------------
// Kernel 3: bilinear sampling + attention-weighted sum.
// One warp per (token, head); lane = channel (HD=32). 4 points x 4 corners of
// coalesced 128B gathers from the value plane (zeros padding, exact match to
// grid_sample align_corners=False / padding_mode='zeros').
// ---------------------------------------------------------------------------
__global__ void __launch_bounds__(256) sample_kernel()
{
    const int gw   = (blockIdx.x * blockDim.x + threadIdx.x) >> 5;
    const int lane = threadIdx.x & 31;
    const int tok  = gw >> 2;         // 0..65535
    const int h    = gw & 3;
    const int b    = tok >> 14;

    const float* vplane = g_value + (size_t)(b * LQ) * DM + h * HDD;
    const int pbase = tok * 16 + h * 4;

    float acc = 0.0f;
#pragma unroll
    for (int p = 0; p < 4; p++) {
        float px = g_px[pbase + p];
        float py = g_py[pbase + p];
        float aw = g_aw[pbase + p];
        float fx = floorf(px), fy = floorf(py);
        int x0 = (int)fx, y0 = (int)fy;
        float wx = px - fx, wy = py - fy;
        float w00 = (1.0f - wx) * (1.0f - wy) * aw;
        float w10 = wx * (1.0f - wy) * aw;
        float w01 = (1.0f - wx) * wy * aw;
        float w11 = wx * wy * aw;

        int x1 = x0 + 1, y1 = y0 + 1;
        bool bx0 = (x0 >= 0) & (x0 < GW);
        bool bx1 = (x1 >= 0) & (x1 < GW);
        bool by0 = (y0 >= 0) & (y0 < GH);
        bool by1 = (y1 >= 0) & (y1 < GH);

        if (bx0 & by0) acc += w00 * vplane[(size_t)(y0 * GW + x0) * DM + lane];
        if (bx1 & by0) acc += w10 * vplane[(size_t)(y0 * GW + x1) * DM + lane];
        if (bx0 & by1) acc += w01 * vplane[(size_t)(y1 * GW + x0) * DM + lane];
        if (bx1 & by1) acc += w11 * vplane[(size_t)(y1 * GW + x1) * DM + lane];
    }
    g_attn[(size_t)tok * DM + h * HDD + lane] = acc;
}

// ---------------------------------------------------------------------------
extern "C" void kernel_launch(void* const* d_in, const int* in_sizes, int n_in,
                              void* d_out, int out_size)
{
    const float* query = (const float*)d_in[0];
    const float* src   = (const float*)d_in[1];
    const float* pos   = (const float*)d_in[2];
    const float* so_w  = (const float*)d_in[3];
    const float* so_b  = (const float*)d_in[4];
    const float* aw_w  = (const float*)d_in[5];
    const float* aw_b  = (const float*)d_in[6];
    const float* vp_w  = (const float*)d_in[7];
    const float* vp_b  = (const float*)d_in[8];
    const float* op_w  = (const float*)d_in[9];
    const float* op_b  = (const float*)d_in[10];
    const float* ln1_g = (const float*)d_in[11];
    const float* ln1_b = (const float*)d_in[12];
    const float* l1_w  = (const float*)d_in[13];
    const float* l1_b  = (const float*)d_in[14];
    const float* l2_w  = (const float*)d_in[15];
    const float* l2_b  = (const float*)d_in[16];
    const float* ln2_g = (const float*)d_in[17];
    const float* ln2_b = (const float*)d_in[18];
    // d_in[19], d_in[20] = H, W (constant 128, hardcoded)

    float *qbuf, *vbuf, *abuf, *hbuf;
    cudaGetSymbolAddress((void**)&qbuf, g_q);
    cudaGetSymbolAddress((void**)&vbuf, g_value);
    cudaGetSymbolAddress((void**)&abuf, g_attn);
    cudaGetSymbolAddress((void**)&hbuf, g_hidden);

    cudaMemcpyAsync(qbuf, query, sizeof(float) * (size_t)NTOK * DM,
                    cudaMemcpyDeviceToDevice, 0);

    for (int l = 0; l < 2; l++) {
        // 1) sampling locations + softmaxed weights
        params_kernel<<<NTOK / 32, 256>>>(pos,
                                          so_w + (size_t)l * DM * 32, so_b + l * 32,
                                          aw_w + (size_t)l * DM * 16, aw_b + l * 16);
        // 2) value projection: src @ vp_w + vp_b
        gemm_k<128, false, false><<<dim3(NTOK / 64, 1), 256>>>(
            src, vp_w + (size_t)l * DM * DM, vp_b + l * DM,
            nullptr, nullptr, nullptr, vbuf, 128);
        // 3) deformable sampling -> attn
        sample_kernel<<<(NTOK * NHH) / 8, 256>>>();
        // 4) output projection + residual + LN1 (in-place into q)
        gemm_k<128, false, true><<<dim3(NTOK / 64, 1), 256>>>(
            abuf, op_w + (size_t)l * DM * DM, op_b + l * DM,
            qbuf, ln1_g + l * DM, ln1_b + l * DM, qbuf, 128);
        // 5) FFN up: relu(q @ l1_w + l1_b)
        gemm_k<128, true, false><<<dim3(NTOK / 64, 4), 256>>>(
            qbuf, l1_w + (size_t)l * DM * FFD, l1_b + l * FFD,
            nullptr, nullptr, nullptr, hbuf, FFD);
        // 6) FFN down + residual + LN2 (in-place into q)
        gemm_k<512, false, true><<<dim3(NTOK / 64, 1), 256>>>(
            hbuf, l2_w + (size_t)l * FFD * DM, l2_b + l * DM,
            qbuf, ln2_g + l * DM, ln2_b + l * DM, qbuf, 128);
    }

    cudaMemcpyAsync(d_out, qbuf, sizeof(float) * (size_t)NTOK * DM,
                    cudaMemcpyDeviceToDevice, 0);
}

// round 4
// speedup vs baseline: 2.2460x; 2.2460x over previous
#include <cuda_runtime.h>
#include <cuda_bf16.h>
#include <math.h>
#include <stdint.h>

// Problem constants
#define NTOK 65536   // B * Lq = 4 * 16384
#define LQ   16384
#define DM   128
#define NHH  4
#define NPP  4
#define HDD  32
#define FFD  512
#define GW   128
#define GH   128

// ---------------- device scratch ----------------
__device__ __align__(16) float g_q[NTOK * DM];            // running query
__device__ __align__(16) float g_value[NTOK * DM];        // value tensor
__device__ __align__(16) float g_attn[NTOK * DM];         // sampled attn
__device__ __align__(16) __nv_bfloat16 g_hid[NTOK * FFD]; // FFN hidden (bf16)
__device__ float g_px[NTOK * NHH * NPP];
__device__ float g_py[NTOK * NHH * NPP];
__device__ float g_aw[NTOK * NHH * NPP];
// bf16 transposed weights: per layer [vp 128x128][op 128x128][l1 512x128][l2 128x512]
#define WB_LAYER 163840
#define WB_VP 0
#define WB_OP 16384
#define WB_L1 32768
#define WB_L2 98304
__device__ __nv_bfloat16 g_wb[2 * WB_LAYER];

// ---------------- helpers ----------------
__device__ __forceinline__ uint32_t smem_u32(const void* p) {
    uint32_t a;
    asm("{ .reg .u64 t; cvta.to.shared.u64 t, %1; cvt.u32.u64 %0, t; }" : "=r"(a) : "l"(p));
    return a;
}
__device__ __forceinline__ uint32_t pack_bf16(float x, float y) {
    __nv_bfloat162 h = __floats2bfloat162_rn(x, y);
    return *(uint32_t*)&h;
}
__device__ __forceinline__ void ldsm4(uint32_t& r0, uint32_t& r1, uint32_t& r2, uint32_t& r3,
                                      uint32_t addr) {
    asm volatile("ldmatrix.sync.aligned.m8n8.x4.shared.b16 {%0,%1,%2,%3}, [%4];"
                 : "=r"(r0), "=r"(r1), "=r"(r2), "=r"(r3) : "r"(addr));
}
__device__ __forceinline__ void mma16816(float* c, uint32_t a0, uint32_t a1, uint32_t a2,
                                         uint32_t a3, uint32_t b0, uint32_t b1) {
    asm volatile(
        "mma.sync.aligned.m16n8k16.row.col.f32.bf16.bf16.f32 "
        "{%0,%1,%2,%3}, {%4,%5,%6,%7}, {%8,%9}, {%0,%1,%2,%3};"
        : "+f"(c[0]), "+f"(c[1]), "+f"(c[2]), "+f"(c[3])
        : "r"(a0), "r"(a1), "r"(a2), "r"(a3), "r"(b0), "r"(b1));
}

// ---------------------------------------------------------------------------
// Weight prep: convert W[K][N] fp32 -> Wb[N][K] bf16 for all 8 matrices.
// ---------------------------------------------------------------------------
__global__ void __launch_bounds__(256) prep_weights(
    const float* __restrict__ vp_w, const float* __restrict__ op_w,
    const float* __restrict__ l1_w, const float* __restrict__ l2_w)
{
    int idx = blockIdx.x * 256 + threadIdx.x;
    if (idx >= 2 * WB_LAYER) return;
    int l = idx / WB_LAYER;
    int r = idx % WB_LAYER;
    const float* W; int K, N, off;
    if (r < 16384)       { W = vp_w + l * 16384; K = 128; N = 128; off = WB_VP; }
    else if (r < 32768)  { W = op_w + l * 16384; r -= 16384; K = 128; N = 128; off = WB_OP; }
    else if (r < 98304)  { W = l1_w + l * 65536; r -= 32768; K = 128; N = 512; off = WB_L1; }
    else                 { W = l2_w + l * 65536; r -= 98304; K = 512; N = 128; off = WB_L2; }
    int n = r / K, k = r % K;
    g_wb[l * WB_LAYER + off + r] = __float2bfloat16(W[k * N + n]);
}

// ---------------------------------------------------------------------------
// HMMA bf16 GEMM: out[128/CTA][128/CTA-col] = A[.][K] @ Wb[N][K]^T (+epilogue)
// 8 warps, warp tile m16 x n128; K staged in 64-wide smem chunks.
// Smem stride 72 elems (144B) -> conflict-free ldmatrix.
// ---------------------------------------------------------------------------
template<int K, int NTOT, bool RELU, bool LN, bool ABF16, bool OBF16>
__global__ void __launch_bounds__(256) gemm_hmma(
    const void* __restrict__ Ain, const __nv_bfloat16* __restrict__ Wb,
    const float* __restrict__ bias, const float* __restrict__ resid,
    const float* __restrict__ lng, const float* __restrict__ lnb,
    void* __restrict__ outv)
{
    __shared__ __align__(16) __nv_bfloat16 sA[128 * 72];
    __shared__ __align__(16) __nv_bfloat16 sB[128 * 72];
    __shared__ float s_bias[128], s_g[128], s_b[128];

    const int tid  = threadIdx.x;
    const int wid  = tid >> 5;
    const int lane = tid & 31;
    const int row0 = blockIdx.x * 128;
    const int n0   = blockIdx.y * 128;

    if (tid < 128) {
        s_bias[tid] = bias[n0 + tid];
        if (LN) { s_g[tid] = lng[tid]; s_b[tid] = lnb[tid]; }
    }

    float c[16][4];
#pragma unroll
    for (int b = 0; b < 16; b++)
#pragma unroll
        for (int j = 0; j < 4; j++) c[b][j] = 0.0f;

    const int lr  = tid >> 4;          // 0..15 used as row group below
    const int lc4 = (tid & 15) * 4;    // 4-elem col group within 64

    for (int kc = 0; kc < K / 64; kc++) {
        if (kc > 0) __syncthreads();
        // stage A (convert fp32->bf16 if needed) and B into smem
#pragma unroll
        for (int i = 0; i < 8; i++) {
            int r = lr + i * 16;       // 0..127
            if (ABF16) {
                uint2 v = *(const uint2*)((const __nv_bfloat16*)Ain +
                                          (size_t)(row0 + r) * K + kc * 64 + lc4);
                *(uint2*)&sA[r * 72 + lc4] = v;
            } else {
                float4 v = *(const float4*)((const float*)Ain +
                                            (size_t)(row0 + r) * K + kc * 64 + lc4);
                uint2 p; p.x = pack_bf16(v.x, v.y); p.y = pack_bf16(v.z, v.w);
                *(uint2*)&sA[r * 72 + lc4] = p;
            }
            uint2 w = *(const uint2*)(Wb + (size_t)(n0 + r) * K + kc * 64 + lc4);
            *(uint2*)&sB[r * 72 + lc4] = w;
        }
        __syncthreads();
        // 4 k16 steps
#pragma unroll
        for (int ks = 0; ks < 4; ks++) {
            uint32_t a0, a1, a2, a3;
            uint32_t aaddr = smem_u32(&sA[(wid * 16 + (lane & 15)) * 72 +
                                          ks * 16 + (lane >> 4) * 8]);
            ldsm4(a0, a1, a2, a3, aaddr);
#pragma unroll
            for (int nb = 0; nb < 8; nb++) {
                uint32_t b0, b1, b2, b3;
                uint32_t baddr = smem_u32(&sB[(nb * 16 + (lane & 15)) * 72 +
                                              ks * 16 + (lane >> 4) * 8]);
                ldsm4(b0, b1, b2, b3, baddr);
                mma16816(c[nb * 2 + 0], a0, a1, a2, a3, b0, b2);
                mma16816(c[nb * 2 + 1], a0, a1, a2, a3, b1, b3);
            }
        }
    }

    // ---------------- epilogue ----------------
    const int qr = lane >> 2;          // 0..7
    const int qc = (lane & 3) * 2;     // 0,2,4,6
    const int r0 = row0 + wid * 16 + qr;
    const int r1 = r0 + 8;

    if (LN) {
        float s0 = 0.f, q0 = 0.f, s1 = 0.f, q1 = 0.f;
#pragma unroll
        for (int b = 0; b < 16; b++) {
            int lcn = b * 8 + qc;
            float2 rv0 = *(const float2*)&resid[(size_t)r0 * 128 + lcn];
            float2 rv1 = *(const float2*)&resid[(size_t)r1 * 128 + lcn];
            c[b][0] += s_bias[lcn]     + rv0.x;
            c[b][1] += s_bias[lcn + 1] + rv0.y;
            c[b][2] += s_bias[lcn]     + rv1.x;
            c[b][3] += s_bias[lcn + 1] + rv1.y;
            s0 += c[b][0] + c[b][1];  q0 += c[b][0] * c[b][0] + c[b][1] * c[b][1];
            s1 += c[b][2] + c[b][3];  q1 += c[b][2] * c[b][2] + c[b][3] * c[b][3];
        }
#pragma unroll
        for (int o = 1; o <= 2; o <<= 1) {
            s0 += __shfl_xor_sync(0xffffffffu, s0, o);
            q0 += __shfl_xor_sync(0xffffffffu, q0, o);
            s1 += __shfl_xor_sync(0xffffffffu, s1, o);
            q1 += __shfl_xor_sync(0xffffffffu, q1, o);
        }
        float m0 = s0 * (1.0f / 128.0f);
        float i0 = rsqrtf(q0 * (1.0f / 128.0f) - m0 * m0 + 1e-5f);
        float m1 = s1 * (1.0f / 128.0f);
        float i1 = rsqrtf(q1 * (1.0f / 128.0f) - m1 * m1 + 1e-5f);
        float* outp = (float*)outv;
#pragma unroll
        for (int b = 0; b < 16; b++) {
            int lcn = b * 8 + qc;
            float2 o0, o1;
            o0.x = (c[b][0] - m0) * i0 * s_g[lcn]     + s_b[lcn];
            o0.y = (c[b][1] - m0) * i0 * s_g[lcn + 1] + s_b[lcn + 1];
            o1.x = (c[b][2] - m1) * i1 * s_g[lcn]     + s_b[lcn];
            o1.y = (c[b][3] - m1) * i1 * s_g[lcn + 1] + s_b[lcn + 1];
            *(float2*)&outp[(size_t)r0 * 128 + lcn] = o0;
            *(float2*)&outp[(size_t)r1 * 128 + lcn] = o1;
        }
    } else {
#pragma unroll
        for (int b = 0; b < 16; b++) {
            int lcn = b * 8 + qc;
            float v0 = c[b][0] + s_bias[lcn];
            float v1 = c[b][1] + s_bias[lcn + 1];
            float v2 = c[b][2] + s_bias[lcn];
            float v3 = c[b][3] + s_bias[lcn + 1];
            if (RELU) {
                v0 = fmaxf(v0, 0.0f); v1 = fmaxf(v1, 0.0f);
                v2 = fmaxf(v2, 0.0f); v3 = fmaxf(v3, 0.0f);
            }
            if (OBF16) {
                __nv_bfloat16* outp = (__nv_bfloat16*)outv;
                *(uint32_t*)&outp[(size_t)r0 * NTOT + n0 + lcn] = pack_bf16(v0, v1);
                *(uint32_t*)&outp[(size_t)r1 * NTOT + n0 + lcn] = pack_bf16(v2, v3);
            } else {
                float* outp = (float*)outv;
                float2 o0; o0.x = v0; o0.y = v1;
                float2 o1; o1.x = v2; o1.y = v3;
                *(float2*)&outp[(size_t)r0 * NTOT + n0 + lcn] = o0;
                *(float2*)&outp[(size_t)r1 * NTOT + n0 + lcn] = o1;
            }
        }
    }
}

// ---------------------------------------------------------------------------
// Sampling params (fp32 FFMA, small)
// ---------------------------------------------------------------------------
__global__ void __launch_bounds__(256) params_kernel(
    const float* __restrict__ pos,
    const float* __restrict__ so_w, const float* __restrict__ so_b,
    const float* __restrict__ aw_w, const float* __restrict__ aw_b)
{
    __shared__ float Ws[DM * 48];
    __shared__ float qs[DM * 33];
    __shared__ float outs[32 * 49];

    const int tid = threadIdx.x;
    const int t0 = blockIdx.x * 32;

    for (int i = tid; i < DM * 48; i += 256) {
        int k = i / 48, o = i % 48;
        Ws[i] = (o < 32) ? so_w[k * 32 + o] : aw_w[k * 16 + (o - 32)];
    }
    for (int i = tid; i < 32 * DM; i += 256) {
        int tok = i >> 7, k = i & 127;
        int gq = t0 + tok;
        qs[k * 33 + tok] = g_q[gq * DM + k] + pos[gq * DM + k];
    }
    __syncthreads();

    const int tok = tid >> 3;
    const int og  = tid & 7;
    float acc[6];
#pragma unroll
    for (int j = 0; j < 6; j++) {
        int o = og * 6 + j;
        acc[j] = (o < 32) ? so_b[o] : aw_b[o - 32];
    }
#pragma unroll 8
    for (int k = 0; k < DM; k++) {
        float a = qs[k * 33 + tok];
#pragma unroll
        for (int j = 0; j < 6; j++)
            acc[j] += a * Ws[k * 48 + og * 6 + j];
    }
#pragma unroll
    for (int j = 0; j < 6; j++) outs[tok * 49 + og * 6 + j] = acc[j];
    __syncthreads();

    if (tid < 128) {
        int tk = tid >> 2, h = tid & 3;
        int gq = t0 + tk;
        float lg0 = outs[tk * 49 + 32 + h * 4 + 0];
        float lg1 = outs[tk * 49 + 32 + h * 4 + 1];
        float lg2 = outs[tk * 49 + 32 + h * 4 + 2];
        float lg3 = outs[tk * 49 + 32 + h * 4 + 3];
        float m = fmaxf(fmaxf(lg0, lg1), fmaxf(lg2, lg3));
        float e0 = expf(lg0 - m), e1 = expf(lg1 - m), e2 = expf(lg2 - m), e3 = expf(lg3 - m);
        float inv = 1.0f / (e0 + e1 + e2 + e3);
        float jx = (float)(gq & (GW - 1));
        float iy = (float)((gq >> 7) & (GH - 1));
        int pbase = gq * 16 + h * 4;
#pragma unroll
        for (int p = 0; p < 4; p++) {
            g_px[pbase + p] = jx + outs[tk * 49 + h * 8 + p * 2 + 0];
            g_py[pbase + p] = iy + outs[tk * 49 + h * 8 + p * 2 + 1];
        }
        g_aw[pbase + 0] = e0 * inv;
        g_aw[pbase + 1] = e1 * inv;
        g_aw[pbase + 2] = e2 * inv;
        g_aw[pbase + 3] = e3 * inv;
    }
}

// ---------------------------------------------------------------------------
// Bilinear sampling + weighted sum
// ---------------------------------------------------------------------------
__global__ void __launch_bounds__(256) sample_kernel()
{
    const int gw   = (blockIdx.x * blockDim.x + threadIdx.x) >> 5;
    const int lane = threadIdx.x & 31;
    const int tok  = gw >> 2;
    const int h    = gw & 3;
    const int b    = tok >> 14;

    const float* vplane = g_value + (size_t)(b * LQ) * DM + h * HDD;
    const int pbase = tok * 16 + h * 4;

    float acc = 0.0f;
#pragma unroll
    for (int p = 0; p < 4; p++) {
        float px = g_px[pbase + p];
        float py = g_py[pbase + p];
        float aw = g_aw[pbase + p];
        float fx = floorf(px), fy = floorf(py);
        int x0 = (int)fx, y0 = (int)fy;
        float wx = px - fx, wy = py - fy;
        float w00 = (1.0f - wx) * (1.0f - wy) * aw;
        float w10 = wx * (1.0f - wy) * aw;
        float w01 = (1.0f - wx) * wy * aw;
        float w11 = wx * wy * aw;

        int x1 = x0 + 1, y1 = y0 + 1;
        bool bx0 = (x0 >= 0) & (x0 < GW);
        bool bx1 = (x1 >= 0) & (x1 < GW);
        bool by0 = (y0 >= 0) & (y0 < GH);
        bool by1 = (y1 >= 0) & (y1 < GH);

        if (bx0 & by0) acc += w00 * vplane[(size_t)(y0 * GW + x0) * DM + lane];
        if (bx1 & by0) acc += w10 * vplane[(size_t)(y0 * GW + x1) * DM + lane];
        if (bx0 & by1) acc += w01 * vplane[(size_t)(y1 * GW + x0) * DM + lane];
        if (bx1 & by1) acc += w11 * vplane[(size_t)(y1 * GW + x1) * DM + lane];
    }
    g_attn[(size_t)tok * DM + h * HDD + lane] = acc;
}

// ---------------------------------------------------------------------------
extern "C" void kernel_launch(void* const* d_in, const int* in_sizes, int n_in,
                              void* d_out, int out_size)
{
    const float* query = (const float*)d_in[0];
    const float* src   = (const float*)d_in[1];
    const float* pos   = (const float*)d_in[2];
    const float* so_w  = (const float*)d_in[3];
    const float* so_b  = (const float*)d_in[4];
    const float* aw_w  = (const float*)d_in[5];
    const float* aw_b  = (const float*)d_in[6];
    const float* vp_w  = (const float*)d_in[7];
    const float* vp_b  = (const float*)d_in[8];
    const float* op_w  = (const float*)d_in[9];
    const float* op_b  = (const float*)d_in[10];
    const float* ln1_g = (const float*)d_in[11];
    const float* ln1_b = (const float*)d_in[12];
    const float* l1_w  = (const float*)d_in[13];
    const float* l1_b  = (const float*)d_in[14];
    const float* l2_w  = (const float*)d_in[15];
    const float* l2_b  = (const float*)d_in[16];
    const float* ln2_g = (const float*)d_in[17];
    const float* ln2_b = (const float*)d_in[18];

    float *qbuf, *vbuf, *abuf;
    __nv_bfloat16 *hbuf, *wbuf;
    cudaGetSymbolAddress((void**)&qbuf, g_q);
    cudaGetSymbolAddress((void**)&vbuf, g_value);
    cudaGetSymbolAddress((void**)&abuf, g_attn);
    cudaGetSymbolAddress((void**)&hbuf, g_hid);
    cudaGetSymbolAddress((void**)&wbuf, g_wb);

    cudaMemcpyAsync(qbuf, query, sizeof(float) * (size_t)NTOK * DM,
                    cudaMemcpyDeviceToDevice, 0);
    prep_weights<<<(2 * WB_LAYER + 255) / 256, 256>>>(vp_w, op_w, l1_w, l2_w);

    for (int l = 0; l < 2; l++) {
        const __nv_bfloat16* wb = wbuf + (size_t)l * WB_LAYER;
        // 1) sampling locations + softmaxed weights
        params_kernel<<<NTOK / 32, 256>>>(pos,
                                          so_w + (size_t)l * DM * 32, so_b + l * 32,
                                          aw_w + (size_t)l * DM * 16, aw_b + l * 16);
        // 2) value projection
        gemm_hmma<128, 128, false, false, false, false><<<dim3(NTOK / 128, 1), 256>>>(
            src, wb + WB_VP, vp_b + l * DM, nullptr, nullptr, nullptr, vbuf);
        // 3) deformable sampling
        sample_kernel<<<(NTOK * NHH) / 8, 256>>>();
        // 4) output projection + residual + LN1 (in-place into q)
        gemm_hmma<128, 128, false, true, false, false><<<dim3(NTOK / 128, 1), 256>>>(
            abuf, wb + WB_OP, op_b + l * DM, qbuf, ln1_g + l * DM, ln1_b + l * DM, qbuf);
        // 5) FFN up: relu -> bf16 hidden
        gemm_hmma<128, 512, true, false, false, true><<<dim3(NTOK / 128, 4), 256>>>(
            qbuf, wb + WB_L1, l1_b + l * FFD, nullptr, nullptr, nullptr, hbuf);
        // 6) FFN down + residual + LN2 (in-place into q)
        gemm_hmma<512, 128, false, true, true, false><<<dim3(NTOK / 128, 1), 256>>>(
            hbuf, wb + WB_L2, l2_b + l * DM, qbuf, ln2_g + l * DM, ln2_b + l * DM, qbuf);
    }

    cudaMemcpyAsync(d_out, qbuf, sizeof(float) * (size_t)NTOK * DM,
                    cudaMemcpyDeviceToDevice, 0);
}

// round 5
// speedup vs baseline: 2.7867x; 1.2407x over previous
#include <cuda_runtime.h>
#include <cuda_bf16.h>
#include <math.h>
#include <stdint.h>

// Problem constants
#define NTOK 65536   // B * Lq = 4 * 16384
#define LQ   16384
#define DM   128
#define NHH  4
#define NPP  4
#define HDD  32
#define FFD  512
#define GW   128
#define GH   128

// ---------------- device scratch ----------------
__device__ __align__(16) float g_q[NTOK * DM];                 // running query
__device__ __align__(16) float g_value[NTOK * DM];             // value tensor
__device__ __align__(16) __nv_bfloat16 g_attn[NTOK * DM];      // sampled attn (bf16)
__device__ float g_px[NTOK * NHH * NPP];
__device__ float g_py[NTOK * NHH * NPP];
__device__ float g_aw[NTOK * NHH * NPP];
// bf16 transposed weights: per layer [vp 128x128][op 128x128][l1 512x128][l2 128x512]
#define WB_LAYER 163840
#define WB_VP 0
#define WB_OP 16384
#define WB_L1 32768
#define WB_L2 98304
__device__ __nv_bfloat16 g_wb[2 * WB_LAYER];

// ---------------- helpers ----------------
__device__ __forceinline__ uint32_t smem_u32(const void* p) {
    uint32_t a;
    asm("{ .reg .u64 t; cvta.to.shared.u64 t, %1; cvt.u32.u64 %0, t; }" : "=r"(a) : "l"(p));
    return a;
}
__device__ __forceinline__ uint32_t pack_bf16(float x, float y) {
    __nv_bfloat162 h = __floats2bfloat162_rn(x, y);
    return *(uint32_t*)&h;
}
__device__ __forceinline__ void ldsm4(uint32_t& r0, uint32_t& r1, uint32_t& r2, uint32_t& r3,
                                      uint32_t addr) {
    asm volatile("ldmatrix.sync.aligned.m8n8.x4.shared.b16 {%0,%1,%2,%3}, [%4];"
                 : "=r"(r0), "=r"(r1), "=r"(r2), "=r"(r3) : "r"(addr));
}
__device__ __forceinline__ void mma16816(float* c, uint32_t a0, uint32_t a1, uint32_t a2,
                                         uint32_t a3, uint32_t b0, uint32_t b1) {
    asm volatile(
        "mma.sync.aligned.m16n8k16.row.col.f32.bf16.bf16.f32 "
        "{%0,%1,%2,%3}, {%4,%5,%6,%7}, {%8,%9}, {%0,%1,%2,%3};"
        : "+f"(c[0]), "+f"(c[1]), "+f"(c[2]), "+f"(c[3])
        : "r"(a0), "r"(a1), "r"(a2), "r"(a3), "r"(b0), "r"(b1));
}

// ---------------------------------------------------------------------------
// Weight prep: convert W[K][N] fp32 -> Wb[N][K] bf16 for all 8 matrices.
// ---------------------------------------------------------------------------
__global__ void __launch_bounds__(256) prep_weights(
    const float* __restrict__ vp_w, const float* __restrict__ op_w,
    const float* __restrict__ l1_w, const float* __restrict__ l2_w)
{
    int idx = blockIdx.x * 256 + threadIdx.x;
    if (idx >= 2 * WB_LAYER) return;
    int l = idx / WB_LAYER;
    int r = idx % WB_LAYER;
    const float* W; int K, N, off;
    if (r < 16384)       { W = vp_w + l * 16384; K = 128; N = 128; off = WB_VP; }
    else if (r < 32768)  { W = op_w + l * 16384; r -= 16384; K = 128; N = 128; off = WB_OP; }
    else if (r < 98304)  { W = l1_w + l * 65536; r -= 32768; K = 128; N = 512; off = WB_L1; }
    else                 { W = l2_w + l * 65536; r -= 98304; K = 512; N = 128; off = WB_L2; }
    int n = r / K, k = r % K;
    g_wb[l * WB_LAYER + off + r] = __float2bfloat16(W[k * N + n]);
}

// ---------------------------------------------------------------------------
// HMMA bf16 GEMM (vp / op): out[128][128] = A[.][128] @ Wb[128][128]^T
// ---------------------------------------------------------------------------
template<int K, int NTOT, bool LN, bool ABF16>
__global__ void __launch_bounds__(256) gemm_hmma(
    const void* __restrict__ Ain, const __nv_bfloat16* __restrict__ Wb,
    const float* __restrict__ bias, const float* __restrict__ resid,
    const float* __restrict__ lng, const float* __restrict__ lnb,
    float* __restrict__ outp)
{
    __shared__ __align__(16) __nv_bfloat16 sA[128 * 72];
    __shared__ __align__(16) __nv_bfloat16 sB[128 * 72];
    __shared__ float s_bias[128], s_g[128], s_b[128];

    const int tid  = threadIdx.x;
    const int wid  = tid >> 5;
    const int lane = tid & 31;
    const int row0 = blockIdx.x * 128;
    const int n0   = 0;

    if (tid < 128) {
        s_bias[tid] = bias[n0 + tid];
        if (LN) { s_g[tid] = lng[tid]; s_b[tid] = lnb[tid]; }
    }

    float c[16][4];
#pragma unroll
    for (int b = 0; b < 16; b++)
#pragma unroll
        for (int j = 0; j < 4; j++) c[b][j] = 0.0f;

    const int lr  = tid >> 4;
    const int lc4 = (tid & 15) * 4;

    for (int kc = 0; kc < K / 64; kc++) {
        if (kc > 0) __syncthreads();
#pragma unroll
        for (int i = 0; i < 8; i++) {
            int r = lr + i * 16;
            if (ABF16) {
                uint2 v = *(const uint2*)((const __nv_bfloat16*)Ain +
                                          (size_t)(row0 + r) * K + kc * 64 + lc4);
                *(uint2*)&sA[r * 72 + lc4] = v;
            } else {
                float4 v = *(const float4*)((const float*)Ain +
                                            (size_t)(row0 + r) * K + kc * 64 + lc4);
                uint2 p; p.x = pack_bf16(v.x, v.y); p.y = pack_bf16(v.z, v.w);
                *(uint2*)&sA[r * 72 + lc4] = p;
            }
            uint2 w = *(const uint2*)(Wb + (size_t)(n0 + r) * K + kc * 64 + lc4);
            *(uint2*)&sB[r * 72 + lc4] = w;
        }
        __syncthreads();
#pragma unroll
        for (int ks = 0; ks < 4; ks++) {
            uint32_t a0, a1, a2, a3;
            uint32_t aaddr = smem_u32(&sA[(wid * 16 + (lane & 15)) * 72 +
                                          ks * 16 + (lane >> 4) * 8]);
            ldsm4(a0, a1, a2, a3, aaddr);
#pragma unroll
            for (int nb = 0; nb < 8; nb++) {
                uint32_t b0, b1, b2, b3;
                uint32_t baddr = smem_u32(&sB[(nb * 16 + (lane & 15)) * 72 +
                                              ks * 16 + (lane >> 4) * 8]);
                ldsm4(b0, b1, b2, b3, baddr);
                mma16816(c[nb * 2 + 0], a0, a1, a2, a3, b0, b2);
                mma16816(c[nb * 2 + 1], a0, a1, a2, a3, b1, b3);
            }
        }
    }

    const int qr = lane >> 2;
    const int qc = (lane & 3) * 2;
    const int r0 = row0 + wid * 16 + qr;
    const int r1 = r0 + 8;

    if (LN) {
        float s0 = 0.f, q0 = 0.f, s1 = 0.f, q1 = 0.f;
#pragma unroll
        for (int b = 0; b < 16; b++) {
            int lcn = b * 8 + qc;
            float2 rv0 = *(const float2*)&resid[(size_t)r0 * 128 + lcn];
            float2 rv1 = *(const float2*)&resid[(size_t)r1 * 128 + lcn];
            c[b][0] += s_bias[lcn]     + rv0.x;
            c[b][1] += s_bias[lcn + 1] + rv0.y;
            c[b][2] += s_bias[lcn]     + rv1.x;
            c[b][3] += s_bias[lcn + 1] + rv1.y;
            s0 += c[b][0] + c[b][1];  q0 += c[b][0] * c[b][0] + c[b][1] * c[b][1];
            s1 += c[b][2] + c[b][3];  q1 += c[b][2] * c[b][2] + c[b][3] * c[b][3];
        }
#pragma unroll
        for (int o = 1; o <= 2; o <<= 1) {
            s0 += __shfl_xor_sync(0xffffffffu, s0, o);
            q0 += __shfl_xor_sync(0xffffffffu, q0, o);
            s1 += __shfl_xor_sync(0xffffffffu, s1, o);
            q1 += __shfl_xor_sync(0xffffffffu, q1, o);
        }
        float m0 = s0 * (1.0f / 128.0f);
        float i0 = rsqrtf(q0 * (1.0f / 128.0f) - m0 * m0 + 1e-5f);
        float m1 = s1 * (1.0f / 128.0f);
        float i1 = rsqrtf(q1 * (1.0f / 128.0f) - m1 * m1 + 1e-5f);
#pragma unroll
        for (int b = 0; b < 16; b++) {
            int lcn = b * 8 + qc;
            float2 o0, o1;
            o0.x = (c[b][0] - m0) * i0 * s_g[lcn]     + s_b[lcn];
            o0.y = (c[b][1] - m0) * i0 * s_g[lcn + 1] + s_b[lcn + 1];
            o1.x = (c[b][2] - m1) * i1 * s_g[lcn]     + s_b[lcn];
            o1.y = (c[b][3] - m1) * i1 * s_g[lcn + 1] + s_b[lcn + 1];
            *(float2*)&outp[(size_t)r0 * 128 + lcn] = o0;
            *(float2*)&outp[(size_t)r1 * 128 + lcn] = o1;
        }
    } else {
#pragma unroll
        for (int b = 0; b < 16; b++) {
            int lcn = b * 8 + qc;
            float2 o0, o1;
            o0.x = c[b][0] + s_bias[lcn];
            o0.y = c[b][1] + s_bias[lcn + 1];
            o1.x = c[b][2] + s_bias[lcn];
            o1.y = c[b][3] + s_bias[lcn + 1];
            *(float2*)&outp[(size_t)r0 * NTOT + n0 + lcn] = o0;
            *(float2*)&outp[(size_t)r1 * NTOT + n0 + lcn] = o1;
        }
    }
}

// ---------------------------------------------------------------------------
// Fused FFN: out = LN(resid + relu(q@W1+b1)@W2 + b2)
// CTA = 128 tokens; hidden (512) processed in 4 chunks of 128 via smem.
// Dynamic smem: sA (q bf16) + sW (W1 chunk -> H) + sW2 (W2 chunk), each
// 2 panels x 128 x 72 bf16 = 36864B -> total 110592B.
// ---------------------------------------------------------------------------
#define FFN_SMEM (3 * 2 * 9216 * 2)
__global__ void __launch_bounds__(256, 1) ffn_fused(
    const float* __restrict__ qin, const __nv_bfloat16* __restrict__ W1,
    const float* __restrict__ b1, const __nv_bfloat16* __restrict__ W2,
    const float* __restrict__ b2, const float* __restrict__ lng,
    const float* __restrict__ lnb, float* __restrict__ outp)
{
    extern __shared__ __align__(16) uint8_t smraw[];
    __nv_bfloat16* sA  = (__nv_bfloat16*)smraw;     // 2*9216
    __nv_bfloat16* sW  = sA + 2 * 9216;             // W1 chunk, then H
    __nv_bfloat16* sW2 = sW + 2 * 9216;             // W2 chunk
    __shared__ float s_b1[128], s_b2[128], s_g[128], s_b[128];

    const int tid  = threadIdx.x;
    const int wid  = tid >> 5;
    const int lane = tid & 31;
    const int row0 = blockIdx.x * 128;
    const int lr   = tid >> 4;
    const int lc4  = (tid & 15) * 4;
    const int qr   = lane >> 2;
    const int qc   = (lane & 3) * 2;

    if (tid < 128) { s_b2[tid] = b2[tid]; s_g[tid] = lng[tid]; s_b[tid] = lnb[tid]; }

    // stage q tile (fp32 -> bf16), 2 panels
#pragma unroll
    for (int p = 0; p < 2; p++)
#pragma unroll
        for (int i = 0; i < 8; i++) {
            int r = lr + i * 16;
            float4 v = *(const float4*)(qin + (size_t)(row0 + r) * 128 + p * 64 + lc4);
            uint2 pk; pk.x = pack_bf16(v.x, v.y); pk.y = pack_bf16(v.z, v.w);
            *(uint2*)&sA[p * 9216 + r * 72 + lc4] = pk;
        }

    float co[16][4];
#pragma unroll
    for (int b = 0; b < 16; b++)
#pragma unroll
        for (int j = 0; j < 4; j++) co[b][j] = 0.0f;

    for (int j = 0; j < 4; j++) {
        if (tid < 128) s_b1[tid] = b1[j * 128 + tid];
        // stage W1 chunk rows j*128..+127
#pragma unroll
        for (int p = 0; p < 2; p++)
#pragma unroll
            for (int i = 0; i < 8; i++) {
                int r = lr + i * 16;
                uint2 w = *(const uint2*)(W1 + (size_t)(j * 128 + r) * 128 + p * 64 + lc4);
                *(uint2*)&sW[p * 9216 + r * 72 + lc4] = w;
            }
        __syncthreads();
        // stage W2 chunk (consumed after a later sync; overlaps MMA1)
#pragma unroll
        for (int p = 0; p < 2; p++)
#pragma unroll
            for (int i = 0; i < 8; i++) {
                int r = lr + i * 16;
                uint2 w = *(const uint2*)(W2 + (size_t)r * 512 + j * 128 + p * 64 + lc4);
                *(uint2*)&sW2[p * 9216 + r * 72 + lc4] = w;
            }
        // MMA1: h = q @ W1_j
        float h[16][4];
#pragma unroll
        for (int b = 0; b < 16; b++)
#pragma unroll
            for (int x = 0; x < 4; x++) h[b][x] = 0.0f;
#pragma unroll
        for (int p = 0; p < 2; p++)
#pragma unroll
            for (int ks = 0; ks < 4; ks++) {
                uint32_t a0, a1, a2, a3;
                uint32_t aaddr = smem_u32(&sA[p * 9216 + (wid * 16 + (lane & 15)) * 72 +
                                              ks * 16 + (lane >> 4) * 8]);
                ldsm4(a0, a1, a2, a3, aaddr);
#pragma unroll
                for (int nb = 0; nb < 8; nb++) {
                    uint32_t b0, b1, b2, b3;
                    uint32_t baddr = smem_u32(&sW[p * 9216 + (nb * 16 + (lane & 15)) * 72 +
                                                  ks * 16 + (lane >> 4) * 8]);
                    ldsm4(b0, b1, b2, b3, baddr);
                    mma16816(h[nb * 2 + 0], a0, a1, a2, a3, b0, b2);
                    mma16816(h[nb * 2 + 1], a0, a1, a2, a3, b1, b3);
                }
            }
        __syncthreads();
        // relu + bias1, pack H (bf16) into sW
        const int hr0 = wid * 16 + qr, hr1 = hr0 + 8;
#pragma unroll
        for (int b = 0; b < 16; b++) {
            int lcn = b * 8 + qc;
            float v0 = fmaxf(h[b][0] + s_b1[lcn],     0.0f);
            float v1 = fmaxf(h[b][1] + s_b1[lcn + 1], 0.0f);
            float v2 = fmaxf(h[b][2] + s_b1[lcn],     0.0f);
            float v3 = fmaxf(h[b][3] + s_b1[lcn + 1], 0.0f);
            int pnl = lcn >> 6, cw = lcn & 63;
            *(uint32_t*)&sW[pnl * 9216 + hr0 * 72 + cw] = pack_bf16(v0, v1);
            *(uint32_t*)&sW[pnl * 9216 + hr1 * 72 + cw] = pack_bf16(v2, v3);
        }
        __syncthreads();
        // MMA2: co += H @ W2_j
#pragma unroll
        for (int p = 0; p < 2; p++)
#pragma unroll
            for (int ks = 0; ks < 4; ks++) {
                uint32_t a0, a1, a2, a3;
                uint32_t aaddr = smem_u32(&sW[p * 9216 + (wid * 16 + (lane & 15)) * 72 +
                                              ks * 16 + (lane >> 4) * 8]);
                ldsm4(a0, a1, a2, a3, aaddr);
#pragma unroll
                for (int nb = 0; nb < 8; nb++) {
                    uint32_t b0, b1, b2, b3;
                    uint32_t baddr = smem_u32(&sW2[p * 9216 + (nb * 16 + (lane & 15)) * 72 +
                                                   ks * 16 + (lane >> 4) * 8]);
                    ldsm4(b0, b1, b2, b3, baddr);
                    mma16816(co[nb * 2 + 0], a0, a1, a2, a3, b0, b2);
                    mma16816(co[nb * 2 + 1], a0, a1, a2, a3, b1, b3);
                }
            }
        __syncthreads();
    }

    // epilogue: bias2 + resid + LN
    const int r0 = row0 + wid * 16 + qr;
    const int r1 = r0 + 8;
    float s0 = 0.f, q0 = 0.f, s1 = 0.f, q1 = 0.f;
#pragma unroll
    for (int b = 0; b < 16; b++) {
        int lcn = b * 8 + qc;
        float2 rv0 = *(const float2*)&qin[(size_t)r0 * 128 + lcn];
        float2 rv1 = *(const float2*)&qin[(size_t)r1 * 128 + lcn];
        co[b][0] += s_b2[lcn]     + rv0.x;
        co[b][1] += s_b2[lcn + 1] + rv0.y;
        co[b][2] += s_b2[lcn]     + rv1.x;
        co[b][3] += s_b2[lcn + 1] + rv1.y;
        s0 += co[b][0] + co[b][1];  q0 += co[b][0] * co[b][0] + co[b][1] * co[b][1];
        s1 += co[b][2] + co[b][3];  q1 += co[b][2] * co[b][2] + co[b][3] * co[b][3];
    }
#pragma unroll
    for (int o = 1; o <= 2; o <<= 1) {
        s0 += __shfl_xor_sync(0xffffffffu, s0, o);
        q0 += __shfl_xor_sync(0xffffffffu, q0, o);
        s1 += __shfl_xor_sync(0xffffffffu, s1, o);
        q1 += __shfl_xor_sync(0xffffffffu, q1, o);
    }
    float m0 = s0 * (1.0f / 128.0f);
    float i0 = rsqrtf(q0 * (1.0f / 128.0f) - m0 * m0 + 1e-5f);
    float m1 = s1 * (1.0f / 128.0f);
    float i1 = rsqrtf(q1 * (1.0f / 128.0f) - m1 * m1 + 1e-5f);
#pragma unroll
    for (int b = 0; b < 16; b++) {
        int lcn = b * 8 + qc;
        float2 o0, o1;
        o0.x = (co[b][0] - m0) * i0 * s_g[lcn]     + s_b[lcn];
        o0.y = (co[b][1] - m0) * i0 * s_g[lcn + 1] + s_b[lcn + 1];
        o1.x = (co[b][2] - m1) * i1 * s_g[lcn]     + s_b[lcn];
        o1.y = (co[b][3] - m1) * i1 * s_g[lcn + 1] + s_b[lcn + 1];
        *(float2*)&outp[(size_t)r0 * 128 + lcn] = o0;
        *(float2*)&outp[(size_t)r1 * 128 + lcn] = o1;
    }
}

// ---------------------------------------------------------------------------
// Sampling params (fp32 FFMA, small) — qsrc parameterized
// ---------------------------------------------------------------------------
__global__ void __launch_bounds__(256) params_kernel(
    const float* __restrict__ qsrc, const float* __restrict__ pos,
    const float* __restrict__ so_w, const float* __restrict__ so_b,
    const float* __restrict__ aw_w, const float* __restrict__ aw_b)
{
    __shared__ float Ws[DM * 48];
    __shared__ float qs[DM * 33];
    __shared__ float outs[32 * 49];

    const int tid = threadIdx.x;
    const int t0 = blockIdx.x * 32;

    for (int i = tid; i < DM * 48; i += 256) {
        int k = i / 48, o = i % 48;
        Ws[i] = (o < 32) ? so_w[k * 32 + o] : aw_w[k * 16 + (o - 32)];
    }
    for (int i = tid; i < 32 * DM; i += 256) {
        int tok = i >> 7, k = i & 127;
        int gq = t0 + tok;
        qs[k * 33 + tok] = qsrc[gq * DM + k] + pos[gq * DM + k];
    }
    __syncthreads();

    const int tok = tid >> 3;
    const int og  = tid & 7;
    float acc[6];
#pragma unroll
    for (int j = 0; j < 6; j++) {
        int o = og * 6 + j;
        acc[j] = (o < 32) ? so_b[o] : aw_b[o - 32];
    }
#pragma unroll 8
    for (int k = 0; k < DM; k++) {
        float a = qs[k * 33 + tok];
#pragma unroll
        for (int j = 0; j < 6; j++)
            acc[j] += a * Ws[k * 48 + og * 6 + j];
    }
#pragma unroll
    for (int j = 0; j < 6; j++) outs[tok * 49 + og * 6 + j] = acc[j];
    __syncthreads();

    if (tid < 128) {
        int tk = tid >> 2, h = tid & 3;
        int gq = t0 + tk;
        float lg0 = outs[tk * 49 + 32 + h * 4 + 0];
        float lg1 = outs[tk * 49 + 32 + h * 4 + 1];
        float lg2 = outs[tk * 49 + 32 + h * 4 + 2];
        float lg3 = outs[tk * 49 + 32 + h * 4 + 3];
        float m = fmaxf(fmaxf(lg0, lg1), fmaxf(lg2, lg3));
        float e0 = expf(lg0 - m), e1 = expf(lg1 - m), e2 = expf(lg2 - m), e3 = expf(lg3 - m);
        float inv = 1.0f / (e0 + e1 + e2 + e3);
        float jx = (float)(gq & (GW - 1));
        float iy = (float)((gq >> 7) & (GH - 1));
        int pbase = gq * 16 + h * 4;
#pragma unroll
        for (int p = 0; p < 4; p++) {
            g_px[pbase + p] = jx + outs[tk * 49 + h * 8 + p * 2 + 0];
            g_py[pbase + p] = iy + outs[tk * 49 + h * 8 + p * 2 + 1];
        }
        g_aw[pbase + 0] = e0 * inv;
        g_aw[pbase + 1] = e1 * inv;
        g_aw[pbase + 2] = e2 * inv;
        g_aw[pbase + 3] = e3 * inv;
    }
}

// ---------------------------------------------------------------------------
// Bilinear sampling: warp = 1 token, lane = (head, 4-channel group), float4.
// Writes bf16 attn.
// ---------------------------------------------------------------------------
__global__ void __launch_bounds__(256) sample_kernel()
{
    const int tok  = (blockIdx.x * 256 + threadIdx.x) >> 5;
    const int lane = threadIdx.x & 31;
    const int h    = lane >> 3;
    const int c8   = lane & 7;
    const int b    = tok >> 14;

    const float* vplane = g_value + (size_t)(b * LQ) * DM + h * HDD + c8 * 4;
    const int pbase = tok * 16 + h * 4;

    float4 acc = {0.f, 0.f, 0.f, 0.f};
#pragma unroll
    for (int p = 0; p < 4; p++) {
        float px = g_px[pbase + p];
        float py = g_py[pbase + p];
        float aw = g_aw[pbase + p];
        float fx = floorf(px), fy = floorf(py);
        int x0 = (int)fx, y0 = (int)fy;
        float wx = px - fx, wy = py - fy;
        float w00 = (1.0f - wx) * (1.0f - wy) * aw;
        float w10 = wx * (1.0f - wy) * aw;
        float w01 = (1.0f - wx) * wy * aw;
        float w11 = wx * wy * aw;

        int x1 = x0 + 1, y1 = y0 + 1;
        bool bx0 = (x0 >= 0) & (x0 < GW);
        bool bx1 = (x1 >= 0) & (x1 < GW);
        bool by0 = (y0 >= 0) & (y0 < GH);
        bool by1 = (y1 >= 0) & (y1 < GH);

        if (bx0 & by0) {
            float4 v = *(const float4*)&vplane[(size_t)(y0 * GW + x0) * DM];
            acc.x += w00 * v.x; acc.y += w00 * v.y; acc.z += w00 * v.z; acc.w += w00 * v.w;
        }
        if (bx1 & by0) {
            float4 v = *(const float4*)&vplane[(size_t)(y0 * GW + x1) * DM];
            acc.x += w10 * v.x; acc.y += w10 * v.y; acc.z += w10 * v.z; acc.w += w10 * v.w;
        }
        if (bx0 & by1) {
            float4 v = *(const float4*)&vplane[(size_t)(y1 * GW + x0) * DM];
            acc.x += w01 * v.x; acc.y += w01 * v.y; acc.z += w01 * v.z; acc.w += w01 * v.w;
        }
        if (bx1 & by1) {
            float4 v = *(const float4*)&vplane[(size_t)(y1 * GW + x1) * DM];
            acc.x += w11 * v.x; acc.y += w11 * v.y; acc.z += w11 * v.z; acc.w += w11 * v.w;
        }
    }
    uint2 pk; pk.x = pack_bf16(acc.x, acc.y); pk.y = pack_bf16(acc.z, acc.w);
    *(uint2*)&g_attn[(size_t)tok * DM + h * HDD + c8 * 4] = pk;
}

// ---------------------------------------------------------------------------
extern "C" void kernel_launch(void* const* d_in, const int* in_sizes, int n_in,
                              void* d_out, int out_size)
{
    const float* query = (const float*)d_in[0];
    const float* src   = (const float*)d_in[1];
    const float* pos   = (const float*)d_in[2];
    const float* so_w  = (const float*)d_in[3];
    const float* so_b  = (const float*)d_in[4];
    const float* aw_w  = (const float*)d_in[5];
    const float* aw_b  = (const float*)d_in[6];
    const float* vp_w  = (const float*)d_in[7];
    const float* vp_b  = (const float*)d_in[8];
    const float* op_w  = (const float*)d_in[9];
    const float* op_b  = (const float*)d_in[10];
    const float* ln1_g = (const float*)d_in[11];
    const float* ln1_b = (const float*)d_in[12];
    const float* l1_b  = (const float*)d_in[14];
    const float* l2_b  = (const float*)d_in[16];
    const float* ln2_g = (const float*)d_in[17];
    const float* ln2_b = (const float*)d_in[18];
    const float* l1_w  = (const float*)d_in[13];
    const float* l2_w  = (const float*)d_in[15];

    float *qbuf, *vbuf;
    __nv_bfloat16 *abuf, *wbuf;
    cudaGetSymbolAddress((void**)&qbuf, g_q);
    cudaGetSymbolAddress((void**)&vbuf, g_value);
    cudaGetSymbolAddress((void**)&abuf, g_attn);
    cudaGetSymbolAddress((void**)&wbuf, g_wb);

    cudaFuncSetAttribute(ffn_fused, cudaFuncAttributeMaxDynamicSharedMemorySize, FFN_SMEM);

    prep_weights<<<(2 * WB_LAYER + 255) / 256, 256>>>(vp_w, op_w, l1_w, l2_w);

    for (int l = 0; l < 2; l++) {
        const __nv_bfloat16* wb = wbuf + (size_t)l * WB_LAYER;
        const float* qsrc = (l == 0) ? query : qbuf;
        float* ffn_out = (l == 0) ? qbuf : (float*)d_out;
        // 1) sampling locations + softmaxed weights
        params_kernel<<<NTOK / 32, 256>>>(qsrc, pos,
                                          so_w + (size_t)l * DM * 32, so_b + l * 32,
                                          aw_w + (size_t)l * DM * 16, aw_b + l * 16);
        // 2) value projection
        gemm_hmma<128, 128, false, false><<<NTOK / 128, 256>>>(
            src, wb + WB_VP, vp_b + l * DM, nullptr, nullptr, nullptr, vbuf);
        // 3) deformable sampling -> bf16 attn
        sample_kernel<<<NTOK / 8, 256>>>();
        // 4) output projection + residual + LN1 -> qbuf
        gemm_hmma<128, 128, true, true><<<NTOK / 128, 256>>>(
            abuf, wb + WB_OP, op_b + l * DM, qsrc, ln1_g + l * DM, ln1_b + l * DM, qbuf);
        // 5+6) fused FFN + residual + LN2
        ffn_fused<<<NTOK / 128, 256, FFN_SMEM>>>(
            qbuf, wb + WB_L1, l1_b + l * FFD, wb + WB_L2, l2_b + l * DM,
            ln2_g + l * DM, ln2_b + l * DM, ffn_out);
    }
}

// round 6
// speedup vs baseline: 2.8421x; 1.0199x over previous
#include <cuda_runtime.h>
#include <cuda_bf16.h>
#include <math.h>
#include <stdint.h>

// Problem constants
#define NTOK 65536   // B * Lq = 4 * 16384
#define LQ   16384
#define DM   128
#define NHH  4
#define NPP  4
#define HDD  32
#define FFD  512
#define GW   128
#define GH   128

// ---------------- device scratch ----------------
__device__ __align__(16) float g_q[NTOK * DM];                     // running query
__device__ __align__(16) __nv_bfloat16 g_value[2 * NTOK * DM];     // value (bf16, both layers)
__device__ float g_px[NTOK * NHH * NPP];
__device__ float g_py[NTOK * NHH * NPP];
__device__ float g_aw[NTOK * NHH * NPP];
// bf16 transposed weights: per layer [vp 128x128][op 128x128][l1 512x128][l2 128x512]
#define WB_LAYER 163840
#define WB_VP 0
#define WB_OP 16384
#define WB_L1 32768
#define WB_L2 98304
__device__ __nv_bfloat16 g_wb[2 * WB_LAYER];

// ---------------- helpers ----------------
__device__ __forceinline__ uint32_t smem_u32(const void* p) {
    uint32_t a;
    asm("{ .reg .u64 t; cvta.to.shared.u64 t, %1; cvt.u32.u64 %0, t; }" : "=r"(a) : "l"(p));
    return a;
}
__device__ __forceinline__ uint32_t pack_bf16(float x, float y) {
    __nv_bfloat162 h = __floats2bfloat162_rn(x, y);
    return *(uint32_t*)&h;
}
__device__ __forceinline__ float2 unpk(uint32_t u) {
    return __bfloat1622float2(*(__nv_bfloat162*)&u);
}
__device__ __forceinline__ void ldsm4(uint32_t& r0, uint32_t& r1, uint32_t& r2, uint32_t& r3,
                                      uint32_t addr) {
    asm volatile("ldmatrix.sync.aligned.m8n8.x4.shared.b16 {%0,%1,%2,%3}, [%4];"
                 : "=r"(r0), "=r"(r1), "=r"(r2), "=r"(r3) : "r"(addr));
}
__device__ __forceinline__ void mma16816(float* c, uint32_t a0, uint32_t a1, uint32_t a2,
                                         uint32_t a3, uint32_t b0, uint32_t b1) {
    asm volatile(
        "mma.sync.aligned.m16n8k16.row.col.f32.bf16.bf16.f32 "
        "{%0,%1,%2,%3}, {%4,%5,%6,%7}, {%8,%9}, {%0,%1,%2,%3};"
        : "+f"(c[0]), "+f"(c[1]), "+f"(c[2]), "+f"(c[3])
        : "r"(a0), "r"(a1), "r"(a2), "r"(a3), "r"(b0), "r"(b1));
}

// ---------------------------------------------------------------------------
// Weight prep: convert W[K][N] fp32 -> Wb[N][K] bf16 for all 8 matrices.
// ---------------------------------------------------------------------------
__global__ void __launch_bounds__(256) prep_weights(
    const float* __restrict__ vp_w, const float* __restrict__ op_w,
    const float* __restrict__ l1_w, const float* __restrict__ l2_w)
{
    int idx = blockIdx.x * 256 + threadIdx.x;
    if (idx >= 2 * WB_LAYER) return;
    int l = idx / WB_LAYER;
    int r = idx % WB_LAYER;
    const float* W; int K, N, off;
    if (r < 16384)       { W = vp_w + l * 16384; K = 128; N = 128; off = WB_VP; }
    else if (r < 32768)  { W = op_w + l * 16384; r -= 16384; K = 128; N = 128; off = WB_OP; }
    else if (r < 98304)  { W = l1_w + l * 65536; r -= 32768; K = 128; N = 512; off = WB_L1; }
    else                 { W = l2_w + l * 65536; r -= 98304; K = 512; N = 128; off = WB_L2; }
    int n = r / K, k = r % K;
    g_wb[l * WB_LAYER + off + r] = __float2bfloat16(W[k * N + n]);
}

// ---------------------------------------------------------------------------
// Value projection for BOTH layers (blockIdx.y = layer): bf16 output.
// ---------------------------------------------------------------------------
__global__ void __launch_bounds__(256) gemm_vp(
    const float* __restrict__ src, const float* __restrict__ vp_b)
{
    __shared__ __align__(16) __nv_bfloat16 sA[128 * 72];
    __shared__ __align__(16) __nv_bfloat16 sB[128 * 72];
    __shared__ float s_bias[128];

    const int tid  = threadIdx.x;
    const int wid  = tid >> 5;
    const int lane = tid & 31;
    const int row0 = blockIdx.x * 128;
    const int layer = blockIdx.y;
    const __nv_bfloat16* Wb = g_wb + (size_t)layer * WB_LAYER + WB_VP;
    __nv_bfloat16* outp = g_value + (size_t)layer * NTOK * DM;

    if (tid < 128) s_bias[tid] = vp_b[layer * DM + tid];

    float c[16][4];
#pragma unroll
    for (int b = 0; b < 16; b++)
#pragma unroll
        for (int j = 0; j < 4; j++) c[b][j] = 0.0f;

    const int lr  = tid >> 4;
    const int lc4 = (tid & 15) * 4;

    for (int kc = 0; kc < 2; kc++) {
        if (kc > 0) __syncthreads();
#pragma unroll
        for (int i = 0; i < 8; i++) {
            int r = lr + i * 16;
            float4 v = *(const float4*)(src + (size_t)(row0 + r) * 128 + kc * 64 + lc4);
            uint2 p; p.x = pack_bf16(v.x, v.y); p.y = pack_bf16(v.z, v.w);
            *(uint2*)&sA[r * 72 + lc4] = p;
            uint2 w = *(const uint2*)(Wb + (size_t)r * 128 + kc * 64 + lc4);
            *(uint2*)&sB[r * 72 + lc4] = w;
        }
        __syncthreads();
#pragma unroll
        for (int ks = 0; ks < 4; ks++) {
            uint32_t a0, a1, a2, a3;
            uint32_t aaddr = smem_u32(&sA[(wid * 16 + (lane & 15)) * 72 +
                                          ks * 16 + (lane >> 4) * 8]);
            ldsm4(a0, a1, a2, a3, aaddr);
#pragma unroll
            for (int nb = 0; nb < 8; nb++) {
                uint32_t b0, b1, b2, b3;
                uint32_t baddr = smem_u32(&sB[(nb * 16 + (lane & 15)) * 72 +
                                              ks * 16 + (lane >> 4) * 8]);
                ldsm4(b0, b1, b2, b3, baddr);
                mma16816(c[nb * 2 + 0], a0, a1, a2, a3, b0, b2);
                mma16816(c[nb * 2 + 1], a0, a1, a2, a3, b1, b3);
            }
        }
    }

    const int qr = lane >> 2;
    const int qc = (lane & 3) * 2;
    const int r0 = row0 + wid * 16 + qr;
    const int r1 = r0 + 8;
#pragma unroll
    for (int b = 0; b < 16; b++) {
        int lcn = b * 8 + qc;
        *(uint32_t*)&outp[(size_t)r0 * 128 + lcn] =
            pack_bf16(c[b][0] + s_bias[lcn], c[b][1] + s_bias[lcn + 1]);
        *(uint32_t*)&outp[(size_t)r1 * 128 + lcn] =
            pack_bf16(c[b][2] + s_bias[lcn], c[b][3] + s_bias[lcn + 1]);
    }
}

// ---------------------------------------------------------------------------
// Fused deformable attention: sample(value) -> smem A tile -> HMMA with op
// weights -> bias + residual + LN -> outp (fp32).
// CTA = 128 tokens. Sampling: warp handles 2 tokens/iter, lane = (half,
// head, 8-ch group); value bf16 gathers of 16B.
// ---------------------------------------------------------------------------
#define ATT_SMEM (4 * 9216 * 2)
__global__ void __launch_bounds__(256, 2) attn_fused(
    const __nv_bfloat16* __restrict__ value, const __nv_bfloat16* __restrict__ Wb,
    const float* __restrict__ bias, const float* __restrict__ resid,
    const float* __restrict__ lng, const float* __restrict__ lnb,
    float* __restrict__ outp)
{
    extern __shared__ __align__(16) uint8_t smraw[];
    __nv_bfloat16* sA = (__nv_bfloat16*)smraw;   // 2 panels x 9216
    __nv_bfloat16* sB = sA + 2 * 9216;           // 2 panels x 9216
    __shared__ float s_bias[128], s_g[128], s_b[128];

    const int tid  = threadIdx.x;
    const int wid  = tid >> 5;
    const int lane = tid & 31;
    const int row0 = blockIdx.x * 128;
    const int batch = row0 >> 14;
    const int lr   = tid >> 4;
    const int lc4  = (tid & 15) * 4;

    if (tid < 128) { s_bias[tid] = bias[tid]; s_g[tid] = lng[tid]; s_b[tid] = lnb[tid]; }

    // stage op weights (2 panels)
#pragma unroll
    for (int p = 0; p < 2; p++)
#pragma unroll
        for (int i = 0; i < 8; i++) {
            int r = lr + i * 16;
            uint2 w = *(const uint2*)(Wb + (size_t)r * 128 + p * 64 + lc4);
            *(uint2*)&sB[p * 9216 + r * 72 + lc4] = w;
        }

    // ---- sampling into sA ----
    const int half = lane >> 4;       // token select within pair
    const int l16  = lane & 15;
    const int h    = l16 >> 2;        // head
    const int cg   = l16 & 3;         // 8-channel group
    const __nv_bfloat16* vplane = value + (size_t)batch * LQ * DM + h * HDD + cg * 8;

#pragma unroll
    for (int it = 0; it < 8; it++) {
        const int rloc = wid * 16 + it * 2 + half;   // local row 0..127
        const int tok  = row0 + rloc;
        const int pbase = tok * 16 + h * 4;

        float a0 = 0.f, a1 = 0.f, a2 = 0.f, a3 = 0.f, a4 = 0.f, a5 = 0.f, a6 = 0.f, a7 = 0.f;
#pragma unroll
        for (int p = 0; p < 4; p++) {
            float px = g_px[pbase + p];
            float py = g_py[pbase + p];
            float aw = g_aw[pbase + p];
            float fx = floorf(px), fy = floorf(py);
            int x0 = (int)fx, y0 = (int)fy;
            float wx = px - fx, wy = py - fy;
            float w00 = (1.0f - wx) * (1.0f - wy) * aw;
            float w10 = wx * (1.0f - wy) * aw;
            float w01 = (1.0f - wx) * wy * aw;
            float w11 = wx * wy * aw;
            int x1 = x0 + 1, y1 = y0 + 1;
            bool bx0 = (x0 >= 0) & (x0 < GW);
            bool bx1 = (x1 >= 0) & (x1 < GW);
            bool by0 = (y0 >= 0) & (y0 < GH);
            bool by1 = (y1 >= 0) & (y1 < GH);
#define GATHER(wgt, xx, yy) do { \
                uint4 v = *(const uint4*)&vplane[((size_t)(yy) * GW + (xx)) * DM]; \
                float2 f0 = unpk(v.x), f1 = unpk(v.y), f2 = unpk(v.z), f3 = unpk(v.w); \
                a0 += (wgt) * f0.x; a1 += (wgt) * f0.y; \
                a2 += (wgt) * f1.x; a3 += (wgt) * f1.y; \
                a4 += (wgt) * f2.x; a5 += (wgt) * f2.y; \
                a6 += (wgt) * f3.x; a7 += (wgt) * f3.y; \
            } while (0)
            if (bx0 & by0) GATHER(w00, x0, y0);
            if (bx1 & by0) GATHER(w10, x1, y0);
            if (bx0 & by1) GATHER(w01, x0, y1);
            if (bx1 & by1) GATHER(w11, x1, y1);
#undef GATHER
        }
        const int c   = h * HDD + cg * 8;
        const int pnl = c >> 6, cw = c & 63;
        uint4 pk;
        pk.x = pack_bf16(a0, a1); pk.y = pack_bf16(a2, a3);
        pk.z = pack_bf16(a4, a5); pk.w = pack_bf16(a6, a7);
        *(uint4*)&sA[pnl * 9216 + rloc * 72 + cw] = pk;
    }
    __syncthreads();

    // ---- HMMA: out = attn @ Wb^T ----
    float cacc[16][4];
#pragma unroll
    for (int b = 0; b < 16; b++)
#pragma unroll
        for (int j = 0; j < 4; j++) cacc[b][j] = 0.0f;

#pragma unroll
    for (int p = 0; p < 2; p++)
#pragma unroll
        for (int ks = 0; ks < 4; ks++) {
            uint32_t a0, a1, a2, a3;
            uint32_t aaddr = smem_u32(&sA[p * 9216 + (wid * 16 + (lane & 15)) * 72 +
                                          ks * 16 + (lane >> 4) * 8]);
            ldsm4(a0, a1, a2, a3, aaddr);
#pragma unroll
            for (int nb = 0; nb < 8; nb++) {
                uint32_t b0, b1, b2, b3;
                uint32_t baddr = smem_u32(&sB[p * 9216 + (nb * 16 + (lane & 15)) * 72 +
                                              ks * 16 + (lane >> 4) * 8]);
                ldsm4(b0, b1, b2, b3, baddr);
                mma16816(cacc[nb * 2 + 0], a0, a1, a2, a3, b0, b2);
                mma16816(cacc[nb * 2 + 1], a0, a1, a2, a3, b1, b3);
            }
        }

    // ---- epilogue: bias + resid + LN ----
    const int qr = lane >> 2;
    const int qc = (lane & 3) * 2;
    const int r0 = row0 + wid * 16 + qr;
    const int r1 = r0 + 8;
    float s0 = 0.f, q0 = 0.f, s1 = 0.f, q1 = 0.f;
#pragma unroll
    for (int b = 0; b < 16; b++) {
        int lcn = b * 8 + qc;
        float2 rv0 = *(const float2*)&resid[(size_t)r0 * 128 + lcn];
        float2 rv1 = *(const float2*)&resid[(size_t)r1 * 128 + lcn];
        cacc[b][0] += s_bias[lcn]     + rv0.x;
        cacc[b][1] += s_bias[lcn + 1] + rv0.y;
        cacc[b][2] += s_bias[lcn]     + rv1.x;
        cacc[b][3] += s_bias[lcn + 1] + rv1.y;
        s0 += cacc[b][0] + cacc[b][1];  q0 += cacc[b][0] * cacc[b][0] + cacc[b][1] * cacc[b][1];
        s1 += cacc[b][2] + cacc[b][3];  q1 += cacc[b][2] * cacc[b][2] + cacc[b][3] * cacc[b][3];
    }
#pragma unroll
    for (int o = 1; o <= 2; o <<= 1) {
        s0 += __shfl_xor_sync(0xffffffffu, s0, o);
        q0 += __shfl_xor_sync(0xffffffffu, q0, o);
        s1 += __shfl_xor_sync(0xffffffffu, s1, o);
        q1 += __shfl_xor_sync(0xffffffffu, q1, o);
    }
    float m0 = s0 * (1.0f / 128.0f);
    float i0 = rsqrtf(q0 * (1.0f / 128.0f) - m0 * m0 + 1e-5f);
    float m1 = s1 * (1.0f / 128.0f);
    float i1 = rsqrtf(q1 * (1.0f / 128.0f) - m1 * m1 + 1e-5f);
#pragma unroll
    for (int b = 0; b < 16; b++) {
        int lcn = b * 8 + qc;
        float2 o0, o1;
        o0.x = (cacc[b][0] - m0) * i0 * s_g[lcn]     + s_b[lcn];
        o0.y = (cacc[b][1] - m0) * i0 * s_g[lcn + 1] + s_b[lcn + 1];
        o1.x = (cacc[b][2] - m1) * i1 * s_g[lcn]     + s_b[lcn];
        o1.y = (cacc[b][3] - m1) * i1 * s_g[lcn + 1] + s_b[lcn + 1];
        *(float2*)&outp[(size_t)r0 * 128 + lcn] = o0;
        *(float2*)&outp[(size_t)r1 * 128 + lcn] = o1;
    }
}

// ---------------------------------------------------------------------------
// Fused FFN: out = LN(resid + relu(q@W1+b1)@W2 + b2)
// ---------------------------------------------------------------------------
#define FFN_SMEM (3 * 2 * 9216 * 2)
__global__ void __launch_bounds__(256, 1) ffn_fused(
    const float* __restrict__ qin, const __nv_bfloat16* __restrict__ W1,
    const float* __restrict__ b1, const __nv_bfloat16* __restrict__ W2,
    const float* __restrict__ b2, const float* __restrict__ lng,
    const float* __restrict__ lnb, float* __restrict__ outp)
{
    extern __shared__ __align__(16) uint8_t smraw[];
    __nv_bfloat16* sA  = (__nv_bfloat16*)smraw;
    __nv_bfloat16* sW  = sA + 2 * 9216;
    __nv_bfloat16* sW2 = sW + 2 * 9216;
    __shared__ float s_b1[128], s_b2[128], s_g[128], s_b[128];

    const int tid  = threadIdx.x;
    const int wid  = tid >> 5;
    const int lane = tid & 31;
    const int row0 = blockIdx.x * 128;
    const int lr   = tid >> 4;
    const int lc4  = (tid & 15) * 4;
    const int qr   = lane >> 2;
    const int qc   = (lane & 3) * 2;

    if (tid < 128) { s_b2[tid] = b2[tid]; s_g[tid] = lng[tid]; s_b[tid] = lnb[tid]; }

#pragma unroll
    for (int p = 0; p < 2; p++)
#pragma unroll
        for (int i = 0; i < 8; i++) {
            int r = lr + i * 16;
            float4 v = *(const float4*)(qin + (size_t)(row0 + r) * 128 + p * 64 + lc4);
            uint2 pk; pk.x = pack_bf16(v.x, v.y); pk.y = pack_bf16(v.z, v.w);
            *(uint2*)&sA[p * 9216 + r * 72 + lc4] = pk;
        }

    float co[16][4];
#pragma unroll
    for (int b = 0; b < 16; b++)
#pragma unroll
        for (int j = 0; j < 4; j++) co[b][j] = 0.0f;

    for (int j = 0; j < 4; j++) {
        if (tid < 128) s_b1[tid] = b1[j * 128 + tid];
#pragma unroll
        for (int p = 0; p < 2; p++)
#pragma unroll
            for (int i = 0; i < 8; i++) {
                int r = lr + i * 16;
                uint2 w = *(const uint2*)(W1 + (size_t)(j * 128 + r) * 128 + p * 64 + lc4);
                *(uint2*)&sW[p * 9216 + r * 72 + lc4] = w;
            }
        __syncthreads();
#pragma unroll
        for (int p = 0; p < 2; p++)
#pragma unroll
            for (int i = 0; i < 8; i++) {
                int r = lr + i * 16;
                uint2 w = *(const uint2*)(W2 + (size_t)r * 512 + j * 128 + p * 64 + lc4);
                *(uint2*)&sW2[p * 9216 + r * 72 + lc4] = w;
            }
        float h[16][4];
#pragma unroll
        for (int b = 0; b < 16; b++)
#pragma unroll
            for (int x = 0; x < 4; x++) h[b][x] = 0.0f;
#pragma unroll
        for (int p = 0; p < 2; p++)
#pragma unroll
            for (int ks = 0; ks < 4; ks++) {
                uint32_t a0, a1, a2, a3;
                uint32_t aaddr = smem_u32(&sA[p * 9216 + (wid * 16 + (lane & 15)) * 72 +
                                              ks * 16 + (lane >> 4) * 8]);
                ldsm4(a0, a1, a2, a3, aaddr);
#pragma unroll
                for (int nb = 0; nb < 8; nb++) {
                    uint32_t b0, b1, b2, b3;
                    uint32_t baddr = smem_u32(&sW[p * 9216 + (nb * 16 + (lane & 15)) * 72 +
                                                  ks * 16 + (lane >> 4) * 8]);
                    ldsm4(b0, b1, b2, b3, baddr);
                    mma16816(h[nb * 2 + 0], a0, a1, a2, a3, b0, b2);
                    mma16816(h[nb * 2 + 1], a0, a1, a2, a3, b1, b3);
                }
            }
        __syncthreads();
        const int hr0 = wid * 16 + qr, hr1 = hr0 + 8;
#pragma unroll
        for (int b = 0; b < 16; b++) {
            int lcn = b * 8 + qc;
            float v0 = fmaxf(h[b][0] + s_b1[lcn],     0.0f);
            float v1 = fmaxf(h[b][1] + s_b1[lcn + 1], 0.0f);
            float v2 = fmaxf(h[b][2] + s_b1[lcn],     0.0f);
            float v3 = fmaxf(h[b][3] + s_b1[lcn + 1], 0.0f);
            int pnl = lcn >> 6, cw = lcn & 63;
            *(uint32_t*)&sW[pnl * 9216 + hr0 * 72 + cw] = pack_bf16(v0, v1);
            *(uint32_t*)&sW[pnl * 9216 + hr1 * 72 + cw] = pack_bf16(v2, v3);
        }
        __syncthreads();
#pragma unroll
        for (int p = 0; p < 2; p++)
#pragma unroll
            for (int ks = 0; ks < 4; ks++) {
                uint32_t a0, a1, a2, a3;
                uint32_t aaddr = smem_u32(&sW[p * 9216 + (wid * 16 + (lane & 15)) * 72 +
                                              ks * 16 + (lane >> 4) * 8]);
                ldsm4(a0, a1, a2, a3, aaddr);
#pragma unroll
                for (int nb = 0; nb < 8; nb++) {
                    uint32_t b0, b1, b2, b3;
                    uint32_t baddr = smem_u32(&sW2[p * 9216 + (nb * 16 + (lane & 15)) * 72 +
                                                   ks * 16 + (lane >> 4) * 8]);
                    ldsm4(b0, b1, b2, b3, baddr);
                    mma16816(co[nb * 2 + 0], a0, a1, a2, a3, b0, b2);
                    mma16816(co[nb * 2 + 1], a0, a1, a2, a3, b1, b3);
                }
            }
        __syncthreads();
    }

    const int r0 = row0 + wid * 16 + qr;
    const int r1 = r0 + 8;
    float s0 = 0.f, q0 = 0.f, s1 = 0.f, q1 = 0.f;
#pragma unroll
    for (int b = 0; b < 16; b++) {
        int lcn = b * 8 + qc;
        float2 rv0 = *(const float2*)&qin[(size_t)r0 * 128 + lcn];
        float2 rv1 = *(const float2*)&qin[(size_t)r1 * 128 + lcn];
        co[b][0] += s_b2[lcn]     + rv0.x;
        co[b][1] += s_b2[lcn + 1] + rv0.y;
        co[b][2] += s_b2[lcn]     + rv1.x;
        co[b][3] += s_b2[lcn + 1] + rv1.y;
        s0 += co[b][0] + co[b][1];  q0 += co[b][0] * co[b][0] + co[b][1] * co[b][1];
        s1 += co[b][2] + co[b][3];  q1 += co[b][2] * co[b][2] + co[b][3] * co[b][3];
    }
#pragma unroll
    for (int o = 1; o <= 2; o <<= 1) {
        s0 += __shfl_xor_sync(0xffffffffu, s0, o);
        q0 += __shfl_xor_sync(0xffffffffu, q0, o);
        s1 += __shfl_xor_sync(0xffffffffu, s1, o);
        q1 += __shfl_xor_sync(0xffffffffu, q1, o);
    }
    float m0 = s0 * (1.0f / 128.0f);
    float i0 = rsqrtf(q0 * (1.0f / 128.0f) - m0 * m0 + 1e-5f);
    float m1 = s1 * (1.0f / 128.0f);
    float i1 = rsqrtf(q1 * (1.0f / 128.0f) - m1 * m1 + 1e-5f);
#pragma unroll
    for (int b = 0; b < 16; b++) {
        int lcn = b * 8 + qc;
        float2 o0, o1;
        o0.x = (co[b][0] - m0) * i0 * s_g[lcn]     + s_b[lcn];
        o0.y = (co[b][1] - m0) * i0 * s_g[lcn + 1] + s_b[lcn + 1];
        o1.x = (co[b][2] - m1) * i1 * s_g[lcn]     + s_b[lcn];
        o1.y = (co[b][3] - m1) * i1 * s_g[lcn + 1] + s_b[lcn + 1];
        *(float2*)&outp[(size_t)r0 * 128 + lcn] = o0;
        *(float2*)&outp[(size_t)r1 * 128 + lcn] = o1;
    }
}

// ---------------------------------------------------------------------------
// Sampling params (fp32 FFMA, small)
// ---------------------------------------------------------------------------
__global__ void __launch_bounds__(256) params_kernel(
    const float* __restrict__ qsrc, const float* __restrict__ pos,
    const float* __restrict__ so_w, const float* __restrict__ so_b,
    const float* __restrict__ aw_w, const float* __restrict__ aw_b)
{
    __shared__ float Ws[DM * 48];
    __shared__ float qs[DM * 33];
    __shared__ float outs[32 * 49];

    const int tid = threadIdx.x;
    const int t0 = blockIdx.x * 32;

    for (int i = tid; i < DM * 48; i += 256) {
        int k = i / 48, o = i % 48;
        Ws[i] = (o < 32) ? so_w[k * 32 + o] : aw_w[k * 16 + (o - 32)];
    }
    for (int i = tid; i < 32 * DM; i += 256) {
        int tok = i >> 7, k = i & 127;
        int gq = t0 + tok;
        qs[k * 33 + tok] = qsrc[gq * DM + k] + pos[gq * DM + k];
    }
    __syncthreads();

    const int tok = tid >> 3;
    const int og  = tid & 7;
    float acc[6];
#pragma unroll
    for (int j = 0; j < 6; j++) {
        int o = og * 6 + j;
        acc[j] = (o < 32) ? so_b[o] : aw_b[o - 32];
    }
#pragma unroll 8
    for (int k = 0; k < DM; k++) {
        float a = qs[k * 33 + tok];
#pragma unroll
        for (int j = 0; j < 6; j++)
            acc[j] += a * Ws[k * 48 + og * 6 + j];
    }
#pragma unroll
    for (int j = 0; j < 6; j++) outs[tok * 49 + og * 6 + j] = acc[j];
    __syncthreads();

    if (tid < 128) {
        int tk = tid >> 2, h = tid & 3;
        int gq = t0 + tk;
        float lg0 = outs[tk * 49 + 32 + h * 4 + 0];
        float lg1 = outs[tk * 49 + 32 + h * 4 + 1];
        float lg2 = outs[tk * 49 + 32 + h * 4 + 2];
        float lg3 = outs[tk * 49 + 32 + h * 4 + 3];
        float m = fmaxf(fmaxf(lg0, lg1), fmaxf(lg2, lg3));
        float e0 = expf(lg0 - m), e1 = expf(lg1 - m), e2 = expf(lg2 - m), e3 = expf(lg3 - m);
        float inv = 1.0f / (e0 + e1 + e2 + e3);
        float jx = (float)(gq & (GW - 1));
        float iy = (float)((gq >> 7) & (GH - 1));
        int pbase = gq * 16 + h * 4;
#pragma unroll
        for (int p = 0; p < 4; p++) {
            g_px[pbase + p] = jx + outs[tk * 49 + h * 8 + p * 2 + 0];
            g_py[pbase + p] = iy + outs[tk * 49 + h * 8 + p * 2 + 1];
        }
        g_aw[pbase + 0] = e0 * inv;
        g_aw[pbase + 1] = e1 * inv;
        g_aw[pbase + 2] = e2 * inv;
        g_aw[pbase + 3] = e3 * inv;
    }
}

// ---------------------------------------------------------------------------
extern "C" void kernel_launch(void* const* d_in, const int* in_sizes, int n_in,
                              void* d_out, int out_size)
{
    const float* query = (const float*)d_in[0];
    const float* src   = (const float*)d_in[1];
    const float* pos   = (const float*)d_in[2];
    const float* so_w  = (const float*)d_in[3];
    const float* so_b  = (const float*)d_in[4];
    const float* aw_w  = (const float*)d_in[5];
    const float* aw_b  = (const float*)d_in[6];
    const float* vp_w  = (const float*)d_in[7];
    const float* vp_b  = (const float*)d_in[8];
    const float* op_w  = (const float*)d_in[9];
    const float* op_b  = (const float*)d_in[10];
    const float* ln1_g = (const float*)d_in[11];
    const float* ln1_b = (const float*)d_in[12];
    const float* l1_w  = (const float*)d_in[13];
    const float* l1_b  = (const float*)d_in[14];
    const float* l2_w  = (const float*)d_in[15];
    const float* l2_b  = (const float*)d_in[16];
    const float* ln2_g = (const float*)d_in[17];
    const float* ln2_b = (const float*)d_in[18];

    float* qbuf;
    __nv_bfloat16 *vbuf, *wbuf;
    cudaGetSymbolAddress((void**)&qbuf, g_q);
    cudaGetSymbolAddress((void**)&vbuf, g_value);
    cudaGetSymbolAddress((void**)&wbuf, g_wb);

    cudaFuncSetAttribute(ffn_fused, cudaFuncAttributeMaxDynamicSharedMemorySize, FFN_SMEM);
    cudaFuncSetAttribute(attn_fused, cudaFuncAttributeMaxDynamicSharedMemorySize, ATT_SMEM);

    prep_weights<<<(2 * WB_LAYER + 255) / 256, 256>>>(vp_w, op_w, l1_w, l2_w);
    // value projection for both layers (src-only dependency)
    gemm_vp<<<dim3(NTOK / 128, 2), 256>>>(src, vp_b);

    for (int l = 0; l < 2; l++) {
        const __nv_bfloat16* wb = wbuf + (size_t)l * WB_LAYER;
        const float* qsrc = (l == 0) ? query : qbuf;
        float* ffn_out = (l == 0) ? qbuf : (float*)d_out;
        // 1) sampling locations + softmaxed weights
        params_kernel<<<NTOK / 32, 256>>>(qsrc, pos,
                                          so_w + (size_t)l * DM * 32, so_b + l * 32,
                                          aw_w + (size_t)l * DM * 16, aw_b + l * 16);
        // 2) fused sample + output projection + residual + LN1 -> qbuf
        attn_fused<<<NTOK / 128, 256, ATT_SMEM>>>(
            vbuf + (size_t)l * NTOK * DM, wb + WB_OP, op_b + l * DM,
            qsrc, ln1_g + l * DM, ln1_b + l * DM, qbuf);
        // 3) fused FFN + residual + LN2
        ffn_fused<<<NTOK / 128, 256, FFN_SMEM>>>(
            qbuf, wb + WB_L1, l1_b + l * FFD, wb + WB_L2, l2_b + l * DM,
            ln2_g + l * DM, ln2_b + l * DM, ffn_out);
    }
}